// round 3
// baseline (speedup 1.0000x reference)
#include <cuda_runtime.h>
#include <cuda_fp16.h>
#include <cstdint>
#include <cstddef>

// ----- problem constants -----
#define LSITES  784
#define CHI     128
#define BATCH   1024
#define NCLS    10
#define KDIM    256               // 2*CHI
#define WROW    264               // padded k-stride of transposed W (halves)
#define SITE_HALVES (CHI * WROW)  // 33792 halves per site
#define SITE_BYTES  (SITE_HALVES * 2)  // 67584 B per site
#define BC      16                // samples per CTA
#define NCTA    (BATCH / BC)      // 64
#define HROW    132               // padded h row stride (floats)
#define AROW    264               // padded A row stride (halves)

// fp16 transposed weights: Wt[site][b][k], k = s*128 + a, row stride WROW
__device__ __half g_Wt[(size_t)LSITES * SITE_HALVES];   // ~50.5 MB static scratch

// ---------------------------------------------------------------------------
// Prepass: W fp32 [n][s][a][b]  ->  fp16 Wt [n][b][k=s*128+a], padded rows
// ---------------------------------------------------------------------------
__global__ void __launch_bounds__(256) prep_kernel(const float* __restrict__ W) {
    extern __shared__ __half sw[];   // [256][132] halves, 67584 B
    const int n   = blockIdx.x;
    const int tid = threadIdx.x;
    const float* Wg = W + (size_t)n * (2 * CHI * CHI);

    // coalesced load + fp16 convert, layout sw[k][b]
    for (int i = 0; i < 128; ++i) {
        int e = i * 256 + tid;            // 0..32767
        int k = e >> 7;
        int b = e & 127;
        sw[k * 132 + b] = __float2half_rn(Wg[e]);
    }
    __syncthreads();

    // transposed, coalesced 16B stores: row b gets k-contiguous halves
    const int w    = tid >> 5;
    const int lane = tid & 31;
    for (int r = 0; r < 16; ++r) {
        int b  = w * 16 + r;
        int k0 = lane * 8;
        __align__(16) __half tmp[8];
#pragma unroll
        for (int j = 0; j < 8; ++j) tmp[j] = sw[(k0 + j) * 132 + b];
        *(uint4*)(&g_Wt[((size_t)n * CHI + b) * WROW + k0]) = *(uint4*)tmp;
    }
}

// ---------------------------------------------------------------------------
// Main kernel: persistent batch slab, sequential sites, fp16 mma.sync
// ---------------------------------------------------------------------------
__global__ void __launch_bounds__(256, 1) mps_kernel(const float* __restrict__ x,
                                                     const float* __restrict__ V,
                                                     float* __restrict__ out) {
    extern __shared__ char smem[];
    __half* Wbuf = (__half*)smem;                                   // [2][SITE_HALVES]
    __half* Abuf = (__half*)(smem + 2 * SITE_BYTES);                // [BC][AROW]
    float*  hbuf = (float*)(smem + 2 * SITE_BYTES + BC * AROW * 2); // [BC][HROW]

    const int tid = threadIdx.x;
    const int cta = blockIdx.x;

    // init h = 1
    for (int i = tid; i < BC * HROW; i += 256) hbuf[i] = 1.0f;

    // ---- A-build role: thread -> (sample row, 16-wide k chunk) ----
    const int tr   = tid >> 4;               // 0..15 sample row within CTA
    const int kb0  = (tid & 15) * 16;        // k chunk base (0..240)
    const int sdim = (kb0 >= CHI) ? 1 : 0;   // which x feature
    const int hc   = kb0 & (CHI - 1);        // h column base
    const int sg   = cta * BC + tr;          // global sample
    const float* xptr = x + ((size_t)sg * 2 + sdim) * LSITES;
    float xv = xptr[0];                      // x for site 0

    // ---- MMA role ----
    const int w    = tid >> 5;               // warp 0..7 -> N range [w*16, w*16+16)
    const int lane = tid & 31;
    const int g    = lane >> 2;
    const int tg   = lane & 3;
    const uint32_t a_lane =
        (uint32_t)__cvta_generic_to_shared(Abuf) +
        (uint32_t)((((lane & 15) * AROW) + ((lane >> 4) * 8)) * 2);
    const int n0 = w * 16 + g;
    const __half* bp0_base0 = Wbuf + n0 * WROW + 2 * tg;
    const __half* bp1_base0 = Wbuf + (n0 + 8) * WROW + 2 * tg;

    float acc[8];
#pragma unroll
    for (int i = 0; i < 8; ++i) acc[i] = 0.f;

    const uint32_t wbuf_s = (uint32_t)__cvta_generic_to_shared(Wbuf);

    // prologue: stage site 0 into buffer 0
    {
        const char* src = (const char*)g_Wt;
        for (int i = 0; i < 17; ++i) {
            int idx = i * 256 + tid;
            if (idx < SITE_BYTES / 16)
                asm volatile("cp.async.cg.shared.global [%0], [%1], 16;\n" ::
                             "r"(wbuf_s + (uint32_t)(idx * 16)),
                             "l"((const void*)(src + idx * 16)) : "memory");
        }
        asm volatile("cp.async.commit_group;\n" ::: "memory");
    }
    __syncthreads();

    for (int n = 0; n < LSITES; ++n) {
        const int p = n & 1;

        // issue W stage for site n+1 into the other buffer
        if (n + 1 < LSITES) {
            const char* src = (const char*)(g_Wt + (size_t)(n + 1) * SITE_HALVES);
            const uint32_t dst = wbuf_s + (uint32_t)((1 - p) * SITE_BYTES);
            for (int i = 0; i < 17; ++i) {
                int idx = i * 256 + tid;
                if (idx < SITE_BYTES / 16)
                    asm volatile("cp.async.cg.shared.global [%0], [%1], 16;\n" ::
                                 "r"(dst + (uint32_t)(idx * 16)),
                                 "l"((const void*)(src + idx * 16)) : "memory");
            }
        }
        asm volatile("cp.async.commit_group;\n" ::: "memory");

        // prefetch x for the next site (L2 latency hidden across the site)
        float xnext = (n + 1 < LSITES) ? __ldg(xptr + (n + 1)) : 0.f;

        // build A[tr][kb0..kb0+15] = fp16( x * h[tr][hc..hc+15] )
        {
            const float4* hv = (const float4*)(hbuf + tr * HROW + hc);
            float4 v0 = hv[0], v1 = hv[1], v2 = hv[2], v3 = hv[3];
            __align__(16) __half2 o[8];
            o[0] = __floats2half2_rn(xv * v0.x, xv * v0.y);
            o[1] = __floats2half2_rn(xv * v0.z, xv * v0.w);
            o[2] = __floats2half2_rn(xv * v1.x, xv * v1.y);
            o[3] = __floats2half2_rn(xv * v1.z, xv * v1.w);
            o[4] = __floats2half2_rn(xv * v2.x, xv * v2.y);
            o[5] = __floats2half2_rn(xv * v2.z, xv * v2.w);
            o[6] = __floats2half2_rn(xv * v3.x, xv * v3.y);
            o[7] = __floats2half2_rn(xv * v3.z, xv * v3.w);
            uint4* ap = (uint4*)(Abuf + tr * AROW + kb0);
            ap[0] = *(uint4*)&o[0];
            ap[1] = *(uint4*)&o[4];
        }

        // wait for this site's W (one group still in flight = next site)
        asm volatile("cp.async.wait_group 1;\n" ::: "memory");
        __syncthreads();

        // MMA: delta(16x128) += A(16x256) @ Wt(256x128), per warp 2 n8 tiles
        {
            const __half* bp0 = bp0_base0 + p * SITE_HALVES;
            const __half* bp1 = bp1_base0 + p * SITE_HALVES;
#pragma unroll
            for (int kb = 0; kb < KDIM; kb += 16) {
                uint32_t a0, a1, a2, a3;
                asm volatile(
                    "ldmatrix.sync.aligned.m8n8.x4.shared.b16 {%0,%1,%2,%3}, [%4];\n"
                    : "=r"(a0), "=r"(a1), "=r"(a2), "=r"(a3)
                    : "r"(a_lane + (uint32_t)(kb * 2)));
                uint32_t b00 = *(const uint32_t*)(bp0 + kb);
                uint32_t b01 = *(const uint32_t*)(bp0 + kb + 8);
                uint32_t b10 = *(const uint32_t*)(bp1 + kb);
                uint32_t b11 = *(const uint32_t*)(bp1 + kb + 8);
                asm volatile(
                    "mma.sync.aligned.m16n8k16.row.col.f32.f16.f16.f32 "
                    "{%0,%1,%2,%3}, {%4,%5,%6,%7}, {%8,%9}, {%0,%1,%2,%3};\n"
                    : "+f"(acc[0]), "+f"(acc[1]), "+f"(acc[2]), "+f"(acc[3])
                    : "r"(a0), "r"(a1), "r"(a2), "r"(a3), "r"(b00), "r"(b01));
                asm volatile(
                    "mma.sync.aligned.m16n8k16.row.col.f32.f16.f16.f32 "
                    "{%0,%1,%2,%3}, {%4,%5,%6,%7}, {%8,%9}, {%0,%1,%2,%3};\n"
                    : "+f"(acc[4]), "+f"(acc[5]), "+f"(acc[6]), "+f"(acc[7])
                    : "r"(a0), "r"(a1), "r"(a2), "r"(a3), "r"(b10), "r"(b11));
            }
        }

        // h += delta (each (row, col) has a unique owner thread)
        {
            const int c0 = w * 16 + 2 * tg;
            float* hr0 = hbuf + g * HROW;
            float* hr1 = hbuf + (g + 8) * HROW;
            float2 t;
            t = *(float2*)(hr0 + c0);     t.x += acc[0]; t.y += acc[1]; *(float2*)(hr0 + c0)     = t;
            t = *(float2*)(hr1 + c0);     t.x += acc[2]; t.y += acc[3]; *(float2*)(hr1 + c0)     = t;
            t = *(float2*)(hr0 + c0 + 8); t.x += acc[4]; t.y += acc[5]; *(float2*)(hr0 + c0 + 8) = t;
            t = *(float2*)(hr1 + c0 + 8); t.x += acc[6]; t.y += acc[7]; *(float2*)(hr1 + c0 + 8) = t;
#pragma unroll
            for (int i = 0; i < 8; ++i) acc[i] = 0.f;
        }
        xv = xnext;
        __syncthreads();
    }

    // classifier: logits = h @ V  (16 samples x 10 classes per CTA)
    if (tid < BC * NCLS) {
        int r = tid / NCLS, c = tid % NCLS;
        const float* hr = hbuf + r * HROW;
        float s = 0.f;
#pragma unroll 8
        for (int a = 0; a < CHI; ++a) s += hr[a] * __ldg(V + a * NCLS + c);
        out[(size_t)(cta * BC + r) * NCLS + c] = s;
    }
}

// ---------------------------------------------------------------------------
extern "C" void kernel_launch(void* const* d_in, const int* in_sizes, int n_in,
                              void* d_out, int out_size) {
    // identify inputs by element count (robust to ordering)
    const float* x = nullptr;  // 1024*2*784   = 1605632
    const float* W = nullptr;  // 784*2*128*128 = 25690112
    const float* V = nullptr;  // 128*10       = 1280
    for (int i = 0; i < n_in; ++i) {
        if (in_sizes[i] == BATCH * 2 * LSITES)            x = (const float*)d_in[i];
        else if (in_sizes[i] == LSITES * 2 * CHI * CHI)   W = (const float*)d_in[i];
        else if (in_sizes[i] == CHI * NCLS)               V = (const float*)d_in[i];
    }
    float* out = (float*)d_out;

    static_assert(2 * SITE_BYTES + BC * AROW * 2 + BC * HROW * 4 == 152064, "smem layout");

    cudaFuncSetAttribute(prep_kernel, cudaFuncAttributeMaxDynamicSharedMemorySize, SITE_BYTES);
    cudaFuncSetAttribute(mps_kernel,  cudaFuncAttributeMaxDynamicSharedMemorySize, 152064);

    prep_kernel<<<LSITES, 256, SITE_BYTES>>>(W);
    mps_kernel<<<NCTA, 256, 152064>>>(x, V, out);
    (void)out_size;
}

// round 4
// speedup vs baseline: 1.1858x; 1.1858x over previous
#include <cuda_runtime.h>
#include <cuda_fp16.h>
#include <cstdint>
#include <cstddef>

// ----- problem constants -----
#define LSITES  784
#define CHI     128
#define BATCH   1024
#define NCLS    10
#define KDIM    256               // 2*CHI
#define WROW    264               // padded k-stride of transposed W (halves)
#define SITE_HALVES (CHI * WROW)  // 33792 halves per site
#define SITE_BYTES  (SITE_HALVES * 2)  // 67584 B per site
#define BC      16                // samples per CTA
#define NCTA    (BATCH / BC)      // 64
#define HROW    132               // padded h row stride (floats)
#define AROW    264               // padded A row stride (halves)
#define SMEM_MBAR_OFF (2 * SITE_BYTES + BC * AROW * 2 + BC * HROW * 4)  // 152064
#define SMEM_TOTAL    (SMEM_MBAR_OFF + 16)

// fp16 transposed weights: Wt[site][b][k], k = s*128 + a, row stride WROW
__device__ __half g_Wt[(size_t)LSITES * SITE_HALVES];   // ~50.5 MB static scratch

// ---------------------------------------------------------------------------
// Prepass: W fp32 [n][s][a][b]  ->  fp16 Wt [n][b][k=s*128+a], padded rows
// ---------------------------------------------------------------------------
__global__ void __launch_bounds__(256) prep_kernel(const float* __restrict__ W) {
    extern __shared__ __half sw[];   // [256][132] halves, 67584 B
    const int n   = blockIdx.x;
    const int tid = threadIdx.x;
    const float* Wg = W + (size_t)n * (2 * CHI * CHI);

    for (int i = 0; i < 128; ++i) {
        int e = i * 256 + tid;
        int k = e >> 7;
        int b = e & 127;
        sw[k * 132 + b] = __float2half_rn(Wg[e]);
    }
    __syncthreads();

    const int w    = tid >> 5;
    const int lane = tid & 31;
    for (int r = 0; r < 16; ++r) {
        int b  = w * 16 + r;
        int k0 = lane * 8;
        __align__(16) __half tmp[8];
#pragma unroll
        for (int j = 0; j < 8; ++j) tmp[j] = sw[(k0 + j) * 132 + b];
        *(uint4*)(&g_Wt[((size_t)n * CHI + b) * WROW + k0]) = *(uint4*)tmp;
    }
}

// ---------------------------------------------------------------------------
__device__ __forceinline__ void mbar_wait(uint32_t mbar, uint32_t parity) {
    asm volatile(
        "{\n\t.reg .pred P;\n"
        "W%=:\n\t"
        "mbarrier.try_wait.parity.acquire.cta.shared::cta.b64 P, [%0], %1, 0x989680;\n\t"
        "@!P bra W%=;\n\t}"
        :: "r"(mbar), "r"(parity) : "memory");
}

// ---------------------------------------------------------------------------
// Main kernel: persistent batch slab, sequential sites, fp16 mma.sync
// ---------------------------------------------------------------------------
__global__ void __launch_bounds__(256, 1) mps_kernel(const float* __restrict__ x,
                                                     const float* __restrict__ V,
                                                     float* __restrict__ out) {
    extern __shared__ char smem[];
    __half* Wbuf = (__half*)smem;                                   // [2][SITE_HALVES]
    __half* Abuf = (__half*)(smem + 2 * SITE_BYTES);                // [BC][AROW]
    float*  hbuf = (float*)(smem + 2 * SITE_BYTES + BC * AROW * 2); // [BC][HROW]
    const uint32_t mb = (uint32_t)__cvta_generic_to_shared(smem + SMEM_MBAR_OFF);

    const int tid = threadIdx.x;
    const int cta = blockIdx.x;

    // init h = 1, init mbarriers
    for (int i = tid; i < BC * HROW; i += 256) hbuf[i] = 1.0f;
    if (tid == 0) {
        asm volatile("mbarrier.init.shared.b64 [%0], 1;" :: "r"(mb)     : "memory");
        asm volatile("mbarrier.init.shared.b64 [%0], 1;" :: "r"(mb + 8) : "memory");
    }
    __syncthreads();

    const uint32_t wbuf_s = (uint32_t)__cvta_generic_to_shared(Wbuf);

    // prologue: stage site 0 into buffer 0 via one bulk copy
    if (tid == 0) {
        asm volatile("mbarrier.arrive.expect_tx.shared.b64 _, [%0], %1;"
                     :: "r"(mb), "r"((uint32_t)SITE_BYTES) : "memory");
        asm volatile(
            "cp.async.bulk.shared::cluster.global.mbarrier::complete_tx::bytes [%0], [%1], %2, [%3];"
            :: "r"(wbuf_s), "l"((const void*)g_Wt), "r"((uint32_t)SITE_BYTES), "r"(mb)
            : "memory");
    }

    // ---- A-build role: thread -> (sample row, 16-wide k chunk) ----
    const int tr   = tid >> 4;               // 0..15 sample row within CTA
    const int kb0  = (tid & 15) * 16;        // k chunk base (0..240)
    const int sdim = (kb0 >= CHI) ? 1 : 0;   // which x feature
    const int hc   = kb0 & (CHI - 1);        // h column base
    const int sg   = cta * BC + tr;          // global sample
    const float* xptr = x + ((size_t)sg * 2 + sdim) * LSITES;
    float xv = __ldg(xptr);                  // x for site 0

    // ---- MMA role ----
    const int w    = tid >> 5;               // warp 0..7 -> N range [w*16, w*16+16)
    const int lane = tid & 31;
    const int g    = lane >> 2;
    const int tg   = lane & 3;
    const uint32_t a_lane =
        (uint32_t)__cvta_generic_to_shared(Abuf) +
        (uint32_t)((((lane & 15) * AROW) + ((lane >> 4) * 8)) * 2);
    // B ldmatrix.x4 lane address: tiles (n0..7,klo)(n0..7,khi)(n8..15,klo)(n8..15,khi)
    const int grp = lane >> 3;
    const int r8  = lane & 7;
    const int bn  = w * 16 + ((grp & 2) ? 8 : 0) + r8;
    const int bk  = (grp & 1) ? 8 : 0;
    const uint32_t b_lane = wbuf_s + (uint32_t)((bn * WROW + bk) * 2);

    float acc[16];
#pragma unroll
    for (int i = 0; i < 16; ++i) acc[i] = 0.f;

    uint32_t ph0 = 0, ph1 = 0;

    for (int n = 0; n < LSITES; ++n) {
        const int p = n & 1;
        const uint32_t mcur = mb + (uint32_t)(p * 8);

        // issue W stage for site n+1 into the other buffer (safe: its previous
        // readers finished before the end-of-site barrier of site n-1)
        if (tid == 0 && n + 1 < LSITES) {
            const uint32_t mnext = mb + (uint32_t)((1 - p) * 8);
            asm volatile("mbarrier.arrive.expect_tx.shared.b64 _, [%0], %1;"
                         :: "r"(mnext), "r"((uint32_t)SITE_BYTES) : "memory");
            asm volatile(
                "cp.async.bulk.shared::cluster.global.mbarrier::complete_tx::bytes [%0], [%1], %2, [%3];"
                :: "r"(wbuf_s + (uint32_t)((1 - p) * SITE_BYTES)),
                   "l"((const void*)(g_Wt + (size_t)(n + 1) * SITE_HALVES)),
                   "r"((uint32_t)SITE_BYTES), "r"(mnext)
                : "memory");
        }

        // prefetch x for the next site
        float xnext = (n + 1 < LSITES) ? __ldg(xptr + (n + 1)) : 0.f;

        // build A[tr][kb0..kb0+15] = fp16( x * h[tr][hc..hc+15] )
        {
            const float4* hv = (const float4*)(hbuf + tr * HROW + hc);
            float4 v0 = hv[0], v1 = hv[1], v2 = hv[2], v3 = hv[3];
            __align__(16) __half2 o[8];
            o[0] = __floats2half2_rn(xv * v0.x, xv * v0.y);
            o[1] = __floats2half2_rn(xv * v0.z, xv * v0.w);
            o[2] = __floats2half2_rn(xv * v1.x, xv * v1.y);
            o[3] = __floats2half2_rn(xv * v1.z, xv * v1.w);
            o[4] = __floats2half2_rn(xv * v2.x, xv * v2.y);
            o[5] = __floats2half2_rn(xv * v2.z, xv * v2.w);
            o[6] = __floats2half2_rn(xv * v3.x, xv * v3.y);
            o[7] = __floats2half2_rn(xv * v3.z, xv * v3.w);
            uint4* ap = (uint4*)(Abuf + tr * AROW + kb0);
            ap[0] = *(uint4*)&o[0];
            ap[1] = *(uint4*)&o[4];
        }

        // wait for this site's W buffer
        mbar_wait(mcur, p ? ph1 : ph0);
        if (p) ph1 ^= 1; else ph0 ^= 1;
        __syncthreads();   // A visible to all warps

        // MMA: delta(16x128) += A(16x256) @ Wt(256x128)
        // 4 independent acc chains: {ntile0,ntile1} x {k<128, k>=128}
        {
            const uint32_t bl = b_lane + (uint32_t)(p * SITE_BYTES);
#pragma unroll
            for (int c = 0; c < 16; ++c) {
                const int kb   = c * 16;
                const int base = (c & 8) ? 8 : 0;
                uint32_t a0, a1, a2, a3, b0, b1, b2, b3;
                asm volatile(
                    "ldmatrix.sync.aligned.m8n8.x4.shared.b16 {%0,%1,%2,%3}, [%4];\n"
                    : "=r"(a0), "=r"(a1), "=r"(a2), "=r"(a3)
                    : "r"(a_lane + (uint32_t)(kb * 2)));
                asm volatile(
                    "ldmatrix.sync.aligned.m8n8.x4.shared.b16 {%0,%1,%2,%3}, [%4];\n"
                    : "=r"(b0), "=r"(b1), "=r"(b2), "=r"(b3)
                    : "r"(bl + (uint32_t)(kb * 2)));
                asm volatile(
                    "mma.sync.aligned.m16n8k16.row.col.f32.f16.f16.f32 "
                    "{%0,%1,%2,%3}, {%4,%5,%6,%7}, {%8,%9}, {%0,%1,%2,%3};\n"
                    : "+f"(acc[base + 0]), "+f"(acc[base + 1]),
                      "+f"(acc[base + 2]), "+f"(acc[base + 3])
                    : "r"(a0), "r"(a1), "r"(a2), "r"(a3), "r"(b0), "r"(b1));
                asm volatile(
                    "mma.sync.aligned.m16n8k16.row.col.f32.f16.f16.f32 "
                    "{%0,%1,%2,%3}, {%4,%5,%6,%7}, {%8,%9}, {%0,%1,%2,%3};\n"
                    : "+f"(acc[base + 4]), "+f"(acc[base + 5]),
                      "+f"(acc[base + 6]), "+f"(acc[base + 7])
                    : "r"(a0), "r"(a1), "r"(a2), "r"(a3), "r"(b2), "r"(b3));
            }
        }

        // combine k-half chains, then h += delta
        {
#pragma unroll
            for (int i = 0; i < 8; ++i) acc[i] += acc[i + 8];
            const int c0 = w * 16 + 2 * tg;
            float* hr0 = hbuf + g * HROW;
            float* hr1 = hbuf + (g + 8) * HROW;
            float2 t;
            t = *(float2*)(hr0 + c0);     t.x += acc[0]; t.y += acc[1]; *(float2*)(hr0 + c0)     = t;
            t = *(float2*)(hr1 + c0);     t.x += acc[2]; t.y += acc[3]; *(float2*)(hr1 + c0)     = t;
            t = *(float2*)(hr0 + c0 + 8); t.x += acc[4]; t.y += acc[5]; *(float2*)(hr0 + c0 + 8) = t;
            t = *(float2*)(hr1 + c0 + 8); t.x += acc[6]; t.y += acc[7]; *(float2*)(hr1 + c0 + 8) = t;
#pragma unroll
            for (int i = 0; i < 16; ++i) acc[i] = 0.f;
        }
        xv = xnext;
        __syncthreads();   // h ready for next site's A-build
    }

    // classifier: logits = h @ V  (16 samples x 10 classes per CTA)
    if (tid < BC * NCLS) {
        int r = tid / NCLS, c = tid % NCLS;
        const float* hr = hbuf + r * HROW;
        float s = 0.f;
#pragma unroll 8
        for (int a = 0; a < CHI; ++a) s += hr[a] * __ldg(V + a * NCLS + c);
        out[(size_t)(cta * BC + r) * NCLS + c] = s;
    }
}

// ---------------------------------------------------------------------------
extern "C" void kernel_launch(void* const* d_in, const int* in_sizes, int n_in,
                              void* d_out, int out_size) {
    const float* x = nullptr;  // 1024*2*784    = 1605632
    const float* W = nullptr;  // 784*2*128*128 = 25690112
    const float* V = nullptr;  // 128*10        = 1280
    for (int i = 0; i < n_in; ++i) {
        if (in_sizes[i] == BATCH * 2 * LSITES)            x = (const float*)d_in[i];
        else if (in_sizes[i] == LSITES * 2 * CHI * CHI)   W = (const float*)d_in[i];
        else if (in_sizes[i] == CHI * NCLS)               V = (const float*)d_in[i];
    }
    float* out = (float*)d_out;

    static_assert(SMEM_TOTAL == 152080, "smem layout");

    cudaFuncSetAttribute(prep_kernel, cudaFuncAttributeMaxDynamicSharedMemorySize, SITE_BYTES);
    cudaFuncSetAttribute(mps_kernel,  cudaFuncAttributeMaxDynamicSharedMemorySize, SMEM_TOTAL);

    prep_kernel<<<LSITES, 256, SITE_BYTES>>>(W);
    mps_kernel<<<NCTA, 256, SMEM_TOTAL>>>(x, V, out);
    (void)out_size;
}

// round 5
// speedup vs baseline: 1.8321x; 1.5450x over previous
#include <cuda_runtime.h>
#include <cuda_fp16.h>
#include <cstdint>
#include <cstddef>

// ----- problem constants -----
#define LSITES  784
#define CHI     128
#define BATCH   1024
#define NCLS    10
#define WROW    264               // padded k-stride of transposed W (halves)
#define SITE_HALVES (CHI * WROW)  // 33792 halves per site
#define SITE_BYTES  (SITE_HALVES * 2)  // 67584 B per site
#define BC      16                // samples per CTA
#define NCTA    (BATCH / BC)      // 64
#define HROW    132               // classifier h row stride (floats)
#define AROW    136               // padded A row stride (halves), K=128
#define ABUF_HALVES (BC * AROW)   // 2176 halves
#define ABUF_BYTES  (ABUF_HALVES * 2)   // 4352
#define SMEM_A_OFF   (2 * SITE_BYTES)           // 135168
#define SMEM_MBAR_OFF (SMEM_A_OFF + 2 * ABUF_BYTES)  // 143872
#define SMEM_TOTAL    (SMEM_MBAR_OFF + 16)      // 143888

// fp16 transposed weights: Wt[site][b][k], k = s*128 + a, row stride WROW
__device__ __half g_Wt[(size_t)LSITES * SITE_HALVES];   // ~50.5 MB static scratch

// ---------------------------------------------------------------------------
// Prepass: W fp32 [n][s][a][b]  ->  fp16 Wt [n][b][k=s*128+a], padded rows
// ---------------------------------------------------------------------------
__global__ void __launch_bounds__(256) prep_kernel(const float* __restrict__ W) {
    extern __shared__ __half sw[];   // [256][132] halves
    const int n   = blockIdx.x;
    const int tid = threadIdx.x;
    const float* Wg = W + (size_t)n * (2 * CHI * CHI);

    for (int i = 0; i < 128; ++i) {
        int e = i * 256 + tid;
        int k = e >> 7;
        int b = e & 127;
        sw[k * 132 + b] = __float2half_rn(Wg[e]);
    }
    __syncthreads();

    const int w    = tid >> 5;
    const int lane = tid & 31;
    for (int r = 0; r < 16; ++r) {
        int b  = w * 16 + r;
        int k0 = lane * 8;
        __align__(16) __half tmp[8];
#pragma unroll
        for (int j = 0; j < 8; ++j) tmp[j] = sw[(k0 + j) * 132 + b];
        *(uint4*)(&g_Wt[((size_t)n * CHI + b) * WROW + k0]) = *(uint4*)tmp;
    }
}

// ---------------------------------------------------------------------------
__device__ __forceinline__ void mbar_wait(uint32_t mbar, uint32_t parity) {
    asm volatile(
        "{\n\t.reg .pred P;\n"
        "W%=:\n\t"
        "mbarrier.try_wait.parity.acquire.cta.shared::cta.b64 P, [%0], %1, 0x989680;\n\t"
        "@!P bra W%=;\n\t}"
        :: "r"(mbar), "r"(parity) : "memory");
}

// ---------------------------------------------------------------------------
// Main kernel: register-resident h, A = fp16(h), x folded post-MMA in f32.
// One __syncthreads per site.
// ---------------------------------------------------------------------------
__global__ void __launch_bounds__(256, 1) mps_kernel(const float* __restrict__ x,
                                                     const float* __restrict__ V,
                                                     float* __restrict__ out) {
    extern __shared__ char smem[];
    __half* Wbuf = (__half*)smem;                       // [2][SITE_HALVES]
    __half* Abuf = (__half*)(smem + SMEM_A_OFF);        // [2][BC][AROW] fp16(h)
    const uint32_t mb = (uint32_t)__cvta_generic_to_shared(smem + SMEM_MBAR_OFF);

    const int tid  = threadIdx.x;
    const int cta  = blockIdx.x;
    const int w    = tid >> 5;               // warp 0..7 -> N range [w*16, w*16+16)
    const int lane = tid & 31;
    const int g    = lane >> 2;              // 0..7
    const int tg   = lane & 3;               // 0..3
    const int c0   = w * 16 + 2 * tg;        // owned h/delta column base

    // h register layout (matches acc fragments):
    //  h[0]=H[g][c0]   h[1]=H[g][c0+1]   h[2]=H[g+8][c0]   h[3]=H[g+8][c0+1]
    //  h[4]=H[g][c0+8] h[5]=H[g][c0+9]   h[6]=H[g+8][c0+8] h[7]=H[g+8][c0+9]
    float h[8];
#pragma unroll
    for (int i = 0; i < 8; ++i) h[i] = 1.0f;

    if (tid == 0) {
        asm volatile("mbarrier.init.shared.b64 [%0], 1;" :: "r"(mb)     : "memory");
        asm volatile("mbarrier.init.shared.b64 [%0], 1;" :: "r"(mb + 8) : "memory");
    }

    // init Abuf[0] = fp16(1)
    {
        const __half2 one2 = __floats2half2_rn(1.f, 1.f);
        *(__half2*)(Abuf + g * AROW + c0)           = one2;
        *(__half2*)(Abuf + g * AROW + c0 + 8)       = one2;
        *(__half2*)(Abuf + (g + 8) * AROW + c0)     = one2;
        *(__half2*)(Abuf + (g + 8) * AROW + c0 + 8) = one2;
    }
    __syncthreads();

    const uint32_t wbuf_s = (uint32_t)__cvta_generic_to_shared(Wbuf);
    const uint32_t abuf_s = (uint32_t)__cvta_generic_to_shared(Abuf);

    // prologue: stage site 0 into buffer 0
    if (tid == 0) {
        asm volatile("mbarrier.arrive.expect_tx.shared.b64 _, [%0], %1;"
                     :: "r"(mb), "r"((uint32_t)SITE_BYTES) : "memory");
        asm volatile(
            "cp.async.bulk.shared::cluster.global.mbarrier::complete_tx::bytes [%0], [%1], %2, [%3];"
            :: "r"(wbuf_s), "l"((const void*)g_Wt), "r"((uint32_t)SITE_BYTES), "r"(mb)
            : "memory");
    }

    // per-thread x streams: samples cta*16+g and cta*16+g+8, features 0/1
    const int sg0 = cta * BC + g;
    const int sg1 = sg0 + 8;
    const float* px00 = x + ((size_t)sg0 * 2 + 0) * LSITES;
    const float* px01 = x + ((size_t)sg0 * 2 + 1) * LSITES;
    const float* px10 = x + ((size_t)sg1 * 2 + 0) * LSITES;
    const float* px11 = x + ((size_t)sg1 * 2 + 1) * LSITES;
    float cx00 = __ldg(px00), cx01 = __ldg(px01);
    float cx10 = __ldg(px10), cx11 = __ldg(px11);

    // ldmatrix lane addresses
    const uint32_t a_base = abuf_s + (uint32_t)((((lane & 15) * AROW) + ((lane >> 4) * 8)) * 2);
    const int grp = lane >> 3;
    const int r8  = lane & 7;
    const int bn  = w * 16 + ((grp & 2) ? 8 : 0) + r8;
    const int bk  = (grp & 1) ? 8 : 0;
    const uint32_t b_base = wbuf_s + (uint32_t)((bn * WROW + bk) * 2);

    uint32_t ph0 = 0, ph1 = 0;

    for (int n = 0; n < LSITES; ++n) {
        const int p = n & 1;

        // issue W stage for site n+1 into the other buffer
        if (tid == 0 && n + 1 < LSITES) {
            const uint32_t mnext = mb + (uint32_t)((1 - p) * 8);
            asm volatile("mbarrier.arrive.expect_tx.shared.b64 _, [%0], %1;"
                         :: "r"(mnext), "r"((uint32_t)SITE_BYTES) : "memory");
            asm volatile(
                "cp.async.bulk.shared::cluster.global.mbarrier::complete_tx::bytes [%0], [%1], %2, [%3];"
                :: "r"(wbuf_s + (uint32_t)((1 - p) * SITE_BYTES)),
                   "l"((const void*)(g_Wt + (size_t)(n + 1) * SITE_HALVES)),
                   "r"((uint32_t)SITE_BYTES), "r"(mnext)
                : "memory");
        }

        // prefetch x for next site
        float nx00 = 0.f, nx01 = 0.f, nx10 = 0.f, nx11 = 0.f;
        if (n + 1 < LSITES) {
            nx00 = __ldg(px00 + n + 1); nx01 = __ldg(px01 + n + 1);
            nx10 = __ldg(px10 + n + 1); nx11 = __ldg(px11 + n + 1);
        }

        // A fragments: 8 chunks of fp16(h), shared by both GEMMs
        uint32_t a[8][4];
        {
            const uint32_t ab = a_base + (uint32_t)(p * ABUF_BYTES);
#pragma unroll
            for (int ca = 0; ca < 8; ++ca) {
                asm volatile(
                    "ldmatrix.sync.aligned.m8n8.x4.shared.b16 {%0,%1,%2,%3}, [%4];\n"
                    : "=r"(a[ca][0]), "=r"(a[ca][1]), "=r"(a[ca][2]), "=r"(a[ca][3])
                    : "r"(ab + (uint32_t)(ca * 32)));
            }
        }

        // wait for this site's W buffer
        mbar_wait(mb + (uint32_t)(p * 8), p ? ph1 : ph0);
        if (p) ph1 ^= 1; else ph0 ^= 1;

        // two GEMMs (s = k-half), 4 independent acc chains of depth 8
        float acc0[8], acc1[8];
#pragma unroll
        for (int i = 0; i < 8; ++i) { acc0[i] = 0.f; acc1[i] = 0.f; }
        {
            const uint32_t bl = b_base + (uint32_t)(p * SITE_BYTES);
#pragma unroll
            for (int c = 0; c < 16; ++c) {
                const int ca = c & 7;
                float* acc = (c & 8) ? acc1 : acc0;
                uint32_t b0, b1, b2, b3;
                asm volatile(
                    "ldmatrix.sync.aligned.m8n8.x4.shared.b16 {%0,%1,%2,%3}, [%4];\n"
                    : "=r"(b0), "=r"(b1), "=r"(b2), "=r"(b3)
                    : "r"(bl + (uint32_t)(c * 32)));
                asm volatile(
                    "mma.sync.aligned.m16n8k16.row.col.f32.f16.f16.f32 "
                    "{%0,%1,%2,%3}, {%4,%5,%6,%7}, {%8,%9}, {%0,%1,%2,%3};\n"
                    : "+f"(acc[0]), "+f"(acc[1]), "+f"(acc[2]), "+f"(acc[3])
                    : "r"(a[ca][0]), "r"(a[ca][1]), "r"(a[ca][2]), "r"(a[ca][3]),
                      "r"(b0), "r"(b1));
                asm volatile(
                    "mma.sync.aligned.m16n8k16.row.col.f32.f16.f16.f32 "
                    "{%0,%1,%2,%3}, {%4,%5,%6,%7}, {%8,%9}, {%0,%1,%2,%3};\n"
                    : "+f"(acc[4]), "+f"(acc[5]), "+f"(acc[6]), "+f"(acc[7])
                    : "r"(a[ca][0]), "r"(a[ca][1]), "r"(a[ca][2]), "r"(a[ca][3]),
                      "r"(b2), "r"(b3));
            }
        }

        // fold: h += x0[row]*delta0 + x1[row]*delta1   (f32, register-only)
        h[0] += cx00 * acc0[0] + cx01 * acc1[0];
        h[1] += cx00 * acc0[1] + cx01 * acc1[1];
        h[2] += cx10 * acc0[2] + cx11 * acc1[2];
        h[3] += cx10 * acc0[3] + cx11 * acc1[3];
        h[4] += cx00 * acc0[4] + cx01 * acc1[4];
        h[5] += cx00 * acc0[5] + cx01 * acc1[5];
        h[6] += cx10 * acc0[6] + cx11 * acc1[6];
        h[7] += cx10 * acc0[7] + cx11 * acc1[7];

        // publish fp16(h) into next site's A buffer
        {
            __half* ad = Abuf + (1 - p) * ABUF_HALVES;
            *(__half2*)(ad + g * AROW + c0)           = __floats2half2_rn(h[0], h[1]);
            *(__half2*)(ad + g * AROW + c0 + 8)       = __floats2half2_rn(h[4], h[5]);
            *(__half2*)(ad + (g + 8) * AROW + c0)     = __floats2half2_rn(h[2], h[3]);
            *(__half2*)(ad + (g + 8) * AROW + c0 + 8) = __floats2half2_rn(h[6], h[7]);
        }

        cx00 = nx00; cx01 = nx01; cx10 = nx10; cx11 = nx11;
        __syncthreads();
    }

    // dump h to smem (reuse Wbuf region) for the classifier
    float* Fh = (float*)smem;   // [16][HROW]
    Fh[g * HROW + c0]           = h[0];
    Fh[g * HROW + c0 + 1]       = h[1];
    Fh[g * HROW + c0 + 8]       = h[4];
    Fh[g * HROW + c0 + 9]       = h[5];
    Fh[(g + 8) * HROW + c0]     = h[2];
    Fh[(g + 8) * HROW + c0 + 1] = h[3];
    Fh[(g + 8) * HROW + c0 + 8] = h[6];
    Fh[(g + 8) * HROW + c0 + 9] = h[7];
    __syncthreads();

    // classifier: logits = h @ V  (16 samples x 10 classes per CTA)
    if (tid < BC * NCLS) {
        int r = tid / NCLS, c = tid % NCLS;
        const float* hr = Fh + r * HROW;
        float s = 0.f;
#pragma unroll 8
        for (int a = 0; a < CHI; ++a) s += hr[a] * __ldg(V + a * NCLS + c);
        out[(size_t)(cta * BC + r) * NCLS + c] = s;
    }
}

// ---------------------------------------------------------------------------
extern "C" void kernel_launch(void* const* d_in, const int* in_sizes, int n_in,
                              void* d_out, int out_size) {
    const float* x = nullptr;  // 1024*2*784    = 1605632
    const float* W = nullptr;  // 784*2*128*128 = 25690112
    const float* V = nullptr;  // 128*10        = 1280
    for (int i = 0; i < n_in; ++i) {
        if (in_sizes[i] == BATCH * 2 * LSITES)            x = (const float*)d_in[i];
        else if (in_sizes[i] == LSITES * 2 * CHI * CHI)   W = (const float*)d_in[i];
        else if (in_sizes[i] == CHI * NCLS)               V = (const float*)d_in[i];
    }
    float* out = (float*)d_out;

    static_assert(SMEM_TOTAL == 143888, "smem layout");

    cudaFuncSetAttribute(prep_kernel, cudaFuncAttributeMaxDynamicSharedMemorySize, SITE_BYTES);
    cudaFuncSetAttribute(mps_kernel,  cudaFuncAttributeMaxDynamicSharedMemorySize, SMEM_TOTAL);

    prep_kernel<<<LSITES, 256, SITE_BYTES>>>(W);
    mps_kernel<<<NCTA, 256, SMEM_TOTAL>>>(x, V, out);
    (void)out_size;
}